// round 17
// baseline (speedup 1.0000x reference)
#include <cuda_runtime.h>
#include <mma.h>

using namespace nvcuda;

#define B_ROWS   131072
#define RES_DIM  100
#define KPAD     104
#define NCH      6
#define H1       128
#define H2       64
#define H3       32
#define CF_ITERS 5
#define CF_K     0.02f

// ---------------- K1: L1 GEMM ----------------
#define K1_TM    128
#define K1_NT    (B_ROWS / K1_TM)      // 1024 tiles
#define A_LD     108                   // res tile ld (pad)
#define W1_LD    132                   // W1 ld (pad)
#define K1_SA    0                     // 128*108 = 13824 floats
#define K1_SW    (K1_SA + K1_TM*A_LD)  // 104*132 = 13728 floats
#define K1_FLOATS (K1_SW + KPAD*W1_LD) // 27552
#define K1_BYTES (K1_FLOATS * 4)       // 110,208 B -> 2 CTAs/SM

// ---------------- K2: L2+L3+L4 fused ----------------
#define K2_TM    64
#define K2_NT    (B_ROWS / K2_TM)      // 2048 tiles
#define H1_LD    132
#define W2_LD    68
#define H2_LD    68
#define W3_LD    36
#define D3_LD    36
#define K2_SH1   0                      // 64*132 = 8448
#define K2_SW2   (K2_SH1 + K2_TM*H1_LD) // 128*68 = 8704
#define K2_SD3   K2_SW2                 // 64*36 = 4608 (reuses W2 after L2... see note: W2 needed through L2 only; D3 written after L3 which reads W3)
#define K2_SH2   (K2_SW2 + H1*W2_LD)    // 64*68 = 4352
#define K2_SW3   (K2_SH2 + K2_TM*H2_LD) // 64*36 = 2304
#define K2_SB1   (K2_SW3 + H2*W3_LD)    // 128
#define K2_SB2   (K2_SB1 + H1)          // 64
#define K2_SB3   (K2_SB2 + H2)          // 32
#define K2_SW4   (K2_SB3 + H3)          // 32
#define K2_SB4   (K2_SW4 + H3)          // 8
#define K2_FLOATS (K2_SB4 + 8)          // 24080
#define K2_BYTES (K2_FLOATS * 4)        // 96,320 B -> 2 CTAs/SM

// intermediate scratch: raw L1 pre-activations [c][B][128]
__device__ float g_h1[(size_t)NCH * B_ROWS * H1];

__device__ __forceinline__ float fsigmoid(float x) {
    return 1.0f / (1.0f + __expf(-x));
}

// ======================================================================
// K1: g_h1[c][m][n] = sum_k res[m][k] * W1[c][k][n]   (raw, no bias/act)
// grid (1024, 6), 256 threads, 2 CTAs/SM
// ======================================================================
__global__ __launch_bounds__(256, 2)
void l1_gemm_kernel(const float* __restrict__ res,
                    const float* __restrict__ W1)
{
    extern __shared__ float sm[];
    float* sA = sm + K1_SA;   // [128 x 104] @ ld 108
    float* sW = sm + K1_SW;   // [104 x 128] @ ld 132

    const int c      = blockIdx.y;
    const int m0     = blockIdx.x * K1_TM;
    const int tid    = threadIdx.x;
    const int warpId = tid >> 5;
    const int wr     = warpId >> 1;   // 0..3 -> 32-row stripes
    const int wc     = warpId & 1;    // 0..1 -> 64-col stripes

    // stage res tile (tf32 pre-rounded, zero-padded K)
    for (int i = tid; i < K1_TM * KPAD; i += 256) {
        int r = i / KPAD;
        int k = i - r * KPAD;
        float v = (k < RES_DIM) ? res[(size_t)(m0 + r) * RES_DIM + k] : 0.0f;
        sA[r * A_LD + k] = wmma::__float_to_tf32(v);
    }
    // stage W1 (tf32 pre-rounded, zero-padded K rows)
    for (int i = tid; i < KPAD * H1; i += 256) {
        int k = i >> 7, n = i & (H1 - 1);
        float v = (k < RES_DIM) ? W1[(size_t)c * RES_DIM * H1 + i] : 0.0f;
        sW[k * W1_LD + n] = wmma::__float_to_tf32(v);
    }
    __syncthreads();

    wmma::fragment<wmma::accumulator, 16, 16, 8, float> acc[2][4];
    #pragma unroll
    for (int i = 0; i < 2; i++)
        #pragma unroll
        for (int j = 0; j < 4; j++) wmma::fill_fragment(acc[i][j], 0.0f);

    #pragma unroll
    for (int kk = 0; kk < KPAD; kk += 8) {
        wmma::fragment<wmma::matrix_a, 16, 16, 8, wmma::precision::tf32, wmma::row_major> a[2];
        wmma::fragment<wmma::matrix_b, 16, 16, 8, wmma::precision::tf32, wmma::row_major> b[4];
        #pragma unroll
        for (int i = 0; i < 2; i++)
            wmma::load_matrix_sync(a[i], sA + (wr * 32 + i * 16) * A_LD + kk, A_LD);
        #pragma unroll
        for (int j = 0; j < 4; j++)
            wmma::load_matrix_sync(b[j], sW + kk * W1_LD + wc * 64 + j * 16, W1_LD);
        #pragma unroll
        for (int i = 0; i < 2; i++)
            #pragma unroll
            for (int j = 0; j < 4; j++)
                wmma::mma_sync(acc[i][j], a[i], b[j], acc[i][j]);
    }

    // store raw accumulators straight to global (bias/silu applied in K2)
    float* outp = g_h1 + ((size_t)c * B_ROWS + m0) * H1;
    #pragma unroll
    for (int i = 0; i < 2; i++)
        #pragma unroll
        for (int j = 0; j < 4; j++)
            wmma::store_matrix_sync(outp + (wr * 32 + i * 16) * H1 + wc * 64 + j * 16,
                                    acc[i][j], H1, wmma::mem_row_major);
}

// ======================================================================
// K2: raw[m][c] = L4(silu(L3-in) ...) over fused L2+L3+L4, 64-row tiles
// grid (2048, 6), 256 threads, 2 CTAs/SM
// ======================================================================
__global__ __launch_bounds__(256, 2)
void l234_kernel(const float* __restrict__ W2, const float* __restrict__ b1,
                 const float* __restrict__ b2,
                 const float* __restrict__ W3, const float* __restrict__ b3,
                 const float* __restrict__ W4, const float* __restrict__ b4,
                 float* __restrict__ raw_out)
{
    extern __shared__ float sm[];
    float* sH1 = sm + K2_SH1;
    float* sW2 = sm + K2_SW2;
    float* sD3 = sm + K2_SD3;   // overlays W2 (safe: written after last W2 read + barrier)
    float* sH2 = sm + K2_SH2;
    float* sW3 = sm + K2_SW3;
    float* sb1 = sm + K2_SB1;
    float* sb2 = sm + K2_SB2;
    float* sb3 = sm + K2_SB3;
    float* sW4 = sm + K2_SW4;
    float* sb4 = sm + K2_SB4;

    const int c      = blockIdx.y;
    const int m0     = blockIdx.x * K2_TM;
    const int tid    = threadIdx.x;
    const int warpId = tid >> 5;

    // biases / small weights
    if (tid < H1)  sb1[tid] = b1[c * H1 + tid];
    if (tid >= H1 && tid < H1 + H2) sb2[tid - H1] = b2[c * H2 + (tid - H1)];
    if (tid >= 192 && tid < 192 + H3) sb3[tid - 192] = b3[c * H3 + (tid - 192)];
    if (tid >= 224 && tid < 224 + H3) sW4[tid - 224] = W4[c * H3 + (tid - 224)];
    if (tid == 0)  sb4[0] = b4[c];

    // stage W2, W3 (tf32)
    for (int i = tid; i < H1 * H2; i += 256) {
        int k = i >> 6, n = i & (H2 - 1);
        sW2[k * W2_LD + n] = wmma::__float_to_tf32(W2[(size_t)c * H1 * H2 + i]);
    }
    for (int i = tid; i < H2 * H3; i += 256) {
        int k = i >> 5, n = i & (H3 - 1);
        sW3[k * W3_LD + n] = wmma::__float_to_tf32(W3[(size_t)c * H2 * H3 + i]);
    }
    __syncthreads();   // sb1 visible before staging uses it

    // stage h1 tile: bias1 + silu + tf32 round during the copy
    {
        const float* hp = g_h1 + ((size_t)c * B_ROWS + m0) * H1;
        for (int i = tid; i < K2_TM * H1; i += 256) {
            int r = i >> 7, k = i & (H1 - 1);
            float h = hp[(size_t)r * H1 + k] + sb1[k];
            sH1[r * H1_LD + k] = wmma::__float_to_tf32(h * fsigmoid(h));
        }
    }
    __syncthreads();

    // L2: [64,128] @ [128,64] -> sH2 (raw). 8 warps: 4 row x 2 col(32)
    {
        const int wr = warpId >> 1;   // 0..3 -> 16-row stripes
        const int wc = warpId & 1;    // 0..1 -> 32-col stripes
        wmma::fragment<wmma::accumulator, 16, 16, 8, float> acc[2];
        #pragma unroll
        for (int j = 0; j < 2; j++) wmma::fill_fragment(acc[j], 0.0f);
        #pragma unroll
        for (int kk = 0; kk < H1; kk += 8) {
            wmma::fragment<wmma::matrix_a, 16, 16, 8, wmma::precision::tf32, wmma::row_major> a;
            wmma::fragment<wmma::matrix_b, 16, 16, 8, wmma::precision::tf32, wmma::row_major> b[2];
            wmma::load_matrix_sync(a, sH1 + (wr * 16) * H1_LD + kk, H1_LD);
            #pragma unroll
            for (int j = 0; j < 2; j++)
                wmma::load_matrix_sync(b[j], sW2 + kk * W2_LD + wc * 32 + j * 16, W2_LD);
            #pragma unroll
            for (int j = 0; j < 2; j++)
                wmma::mma_sync(acc[j], a, b[j], acc[j]);
        }
        #pragma unroll
        for (int j = 0; j < 2; j++)
            wmma::store_matrix_sync(sH2 + (wr * 16) * H2_LD + wc * 32 + j * 16,
                                    acc[j], H2_LD, wmma::mem_row_major);
    }
    __syncthreads();

    // bias2 + silu + round (in place)
    for (int i = tid; i < K2_TM * H2; i += 256) {
        int r = i >> 6, n = i & (H2 - 1);
        float h = sH2[r * H2_LD + n] + sb2[n];
        sH2[r * H2_LD + n] = wmma::__float_to_tf32(h * fsigmoid(h));
    }
    __syncthreads();   // also: last read of sW2 region is done -> sD3 may overwrite

    // L3: [64,64] @ [64,32] -> sD3 (raw). 8 warps: 4 row x 2 col(16)
    {
        const int wr = warpId >> 1;
        const int wc = warpId & 1;
        wmma::fragment<wmma::accumulator, 16, 16, 8, float> acc;
        wmma::fill_fragment(acc, 0.0f);
        #pragma unroll
        for (int kk = 0; kk < H2; kk += 8) {
            wmma::fragment<wmma::matrix_a, 16, 16, 8, wmma::precision::tf32, wmma::row_major> a;
            wmma::fragment<wmma::matrix_b, 16, 16, 8, wmma::precision::tf32, wmma::row_major> b;
            wmma::load_matrix_sync(a, sH2 + (wr * 16) * H2_LD + kk, H2_LD);
            wmma::load_matrix_sync(b, sW3 + kk * W3_LD + wc * 16, W3_LD);
            wmma::mma_sync(acc, a, b, acc);
        }
        wmma::store_matrix_sync(sD3 + (wr * 16) * D3_LD + wc * 16, acc, D3_LD,
                                wmma::mem_row_major);
    }
    __syncthreads();

    // L4: per-row dot with bias3+silu fused
    if (tid < K2_TM) {
        float accv = sb4[0];
        #pragma unroll
        for (int j = 0; j < H3; j++) {
            int jj = (j + tid) & (H3 - 1);   // rotation: conflict-light at ld 36
            float v = sD3[tid * D3_LD + jj] + sb3[jj];
            accv += (v * fsigmoid(v)) * sW4[jj];
        }
        raw_out[(size_t)(m0 + tid) * NCH + c] = accv;
    }
}

// ======================================================================
// coupling fixed point
// ======================================================================
__global__ __launch_bounds__(256)
void coupling_kernel(const float* __restrict__ raw,
                     const float* __restrict__ coupling,
                     const float* __restrict__ decay,
                     float* __restrict__ act_out)
{
    __shared__ float sc[NCH * NCH];
    __shared__ float sd[NCH];
    if (threadIdx.x < NCH * NCH) sc[threadIdx.x] = coupling[threadIdx.x] * CF_K;
    if (threadIdx.x < NCH)       sd[threadIdx.x] = decay[threadIdx.x];
    __syncthreads();

    const int b = blockIdx.x * blockDim.x + threadIdx.x;
    if (b >= B_ROWS) return;

    float r[NCH], a[NCH];
    #pragma unroll
    for (int j = 0; j < NCH; j++) {
        r[j] = raw[(size_t)b * NCH + j];
        a[j] = fsigmoid(r[j]);
    }
    #pragma unroll
    for (int it = 0; it < CF_ITERS; it++) {
        float d[NCH];
        #pragma unroll
        for (int j = 0; j < NCH; j++) d[j] = 0.0f;
        #pragma unroll
        for (int i = 0; i < NCH; i++) {
            float w = a[i] * sd[i];
            #pragma unroll
            for (int j = 0; j < NCH; j++) d[j] += w * sc[i * NCH + j];
        }
        #pragma unroll
        for (int j = 0; j < NCH; j++) a[j] = fsigmoid(r[j] + d[j]);
    }
    #pragma unroll
    for (int j = 0; j < NCH; j++) act_out[(size_t)b * NCH + j] = a[j];
}

extern "C" void kernel_launch(void* const* d_in, const int* in_sizes, int n_in,
                              void* d_out, int out_size) {
    const float* res      = (const float*)d_in[0];
    const float* W1       = (const float*)d_in[1];
    const float* b1       = (const float*)d_in[2];
    const float* W2       = (const float*)d_in[3];
    const float* b2       = (const float*)d_in[4];
    const float* W3       = (const float*)d_in[5];
    const float* b3       = (const float*)d_in[6];
    const float* W4       = (const float*)d_in[7];
    const float* b4       = (const float*)d_in[8];
    const float* coupling = (const float*)d_in[9];
    const float* decay    = (const float*)d_in[10];

    float* out     = (float*)d_out;
    float* act_out = out;                                // act (B,6)
    float* raw_out = out + (size_t)B_ROWS * NCH;         // raw (B,6)

    cudaFuncSetAttribute(l1_gemm_kernel,
                         cudaFuncAttributeMaxDynamicSharedMemorySize, K1_BYTES);
    cudaFuncSetAttribute(l234_kernel,
                         cudaFuncAttributeMaxDynamicSharedMemorySize, K2_BYTES);

    dim3 g1(K1_NT, NCH);   // 1024 x 6 CTAs
    l1_gemm_kernel<<<g1, 256, K1_BYTES>>>(res, W1);

    dim3 g2(K2_NT, NCH);   // 2048 x 6 CTAs
    l234_kernel<<<g2, 256, K2_BYTES>>>(W2, b1, b2, W3, b3, W4, b4, raw_out);

    coupling_kernel<<<B_ROWS / 256, 256>>>(raw_out, coupling, decay, act_out);
}